// round 1
// baseline (speedup 1.0000x reference)
#include <cuda_runtime.h>
#include <math.h>

// Shapes (fixed by the problem)
#define B_SZ 1024
#define S_SZ 512
#define H_SZ 512
#define D_SZ 2048

#define THREADS 512
#define NWARPS (THREADS / 32)

__device__ __forceinline__ float sigmoidf_fast(float x) {
    return 1.0f / (1.0f + __expf(-x));
}

__global__ __launch_bounds__(THREADS, 2)
void hallucination_kernel(const float* __restrict__ routing_entropy,
                          const float* __restrict__ moe_confidence,
                          const float* __restrict__ memory_mismatch,
                          const float* __restrict__ hidden_states,
                          const float* __restrict__ routing_repr,
                          const float* __restrict__ probe_w,
                          const float* __restrict__ probe_b,
                          float* __restrict__ out)
{
    const int b    = blockIdx.x;
    const int tid  = threadIdx.x;
    const int warp = tid >> 5;
    const int lane = tid & 31;

    __shared__ float s_w[H_SZ];
    __shared__ float s_sig[NWARPS];
    __shared__ float s_nrm[NWARPS];

    // Stage probe weights in shared memory (one element per thread, H == THREADS)
    s_w[tid] = probe_w[tid];
    __syncthreads();

    const float pb = probe_b[0];
    const float4* __restrict__ w4   = reinterpret_cast<const float4*>(s_w);
    const float4* __restrict__ hid4 =
        reinterpret_cast<const float4*>(hidden_states + (size_t)b * S_SZ * H_SZ);

    // ---- semantic entropy: per-token dot -> sigmoid -> mean over S ----
    float sig_sum = 0.0f;
    for (int s = warp; s < S_SZ; s += NWARPS) {
        const float4* __restrict__ row = hid4 + (size_t)s * (H_SZ / 4);
        float dot = 0.0f;
        #pragma unroll
        for (int k = 0; k < 4; ++k) {
            float4 h = row[lane + k * 32];
            float4 w = w4[lane + k * 32];
            dot = fmaf(h.x, w.x, dot);
            dot = fmaf(h.y, w.y, dot);
            dot = fmaf(h.z, w.z, dot);
            dot = fmaf(h.w, w.w, dot);
        }
        #pragma unroll
        for (int off = 16; off > 0; off >>= 1)
            dot += __shfl_xor_sync(0xffffffffu, dot, off);
        // every lane now has the full dot; only lane 0 accumulates
        if (lane == 0)
            sig_sum += sigmoidf_fast(dot + pb);
    }
    if (lane == 0) s_sig[warp] = sig_sum;

    // ---- routing_repr L2 norm: D = 2048 floats = 512 float4 = one per thread ----
    {
        const float4* __restrict__ r4 =
            reinterpret_cast<const float4*>(routing_repr + (size_t)b * D_SZ);
        float4 v = r4[tid];
        float n = v.x * v.x + v.y * v.y + v.z * v.z + v.w * v.w;
        #pragma unroll
        for (int off = 16; off > 0; off >>= 1)
            n += __shfl_xor_sync(0xffffffffu, n, off);
        if (lane == 0) s_nrm[warp] = n;
    }
    __syncthreads();

    if (tid == 0) {
        float sem = 0.0f, n2 = 0.0f;
        #pragma unroll
        for (int w = 0; w < NWARPS; ++w) { sem += s_sig[w]; n2 += s_nrm[w]; }
        sem *= (1.0f / (float)S_SZ);

        const float sv        = sqrtf(n2);
        const float eigen     = 1.0f / (sv + 1e-8f);
        const float norm_eig  = sigmoidf_fast(eigen - 1.0f);

        const float MAX_ENTROPY = 2.0794415416798357f;   // ln(8)
        const float ne = routing_entropy[b] / MAX_ENTROPY;
        const float ic = 1.0f - moe_confidence[b];
        const float nm = sigmoidf_fast(memory_mismatch[b] - 2.0f);

        float risk = 0.25f * ne
                   - 0.20f * ic
                   + 0.20f * nm
                   + 0.20f * sem
                   + 0.15f * norm_eig;
        out[b] = fminf(fmaxf(risk, 0.0f), 1.0f);
    }
}

extern "C" void kernel_launch(void* const* d_in, const int* in_sizes, int n_in,
                              void* d_out, int out_size)
{
    // metadata order: routing_entropy, moe_confidence, memory_mismatch,
    //                 memory_loss (unused), hidden_states, routing_repr,
    //                 probe_w, probe_b
    const float* routing_entropy = (const float*)d_in[0];
    const float* moe_confidence  = (const float*)d_in[1];
    const float* memory_mismatch = (const float*)d_in[2];
    // d_in[3] = memory_loss (unused by reference)
    const float* hidden_states   = (const float*)d_in[4];
    const float* routing_repr    = (const float*)d_in[5];
    const float* probe_w         = (const float*)d_in[6];
    const float* probe_b         = (const float*)d_in[7];
    float* out = (float*)d_out;

    hallucination_kernel<<<B_SZ, THREADS>>>(routing_entropy, moe_confidence,
                                            memory_mismatch, hidden_states,
                                            routing_repr, probe_w, probe_b, out);
}

// round 2
// speedup vs baseline: 1.0589x; 1.0589x over previous
#include <cuda_runtime.h>
#include <math.h>

// Shapes (fixed by the problem)
#define B_SZ 1024
#define S_SZ 512
#define H_SZ 512
#define D_SZ 2048

#define THREADS 512
#define NWARPS (THREADS / 32)
#define ITERS  (S_SZ / NWARPS)   // 32 tokens per warp

__device__ __forceinline__ float sigmoidf_fast(float x) {
    return 1.0f / (1.0f + __expf(-x));
}

__global__ __launch_bounds__(THREADS, 2)
void hallucination_kernel(const float* __restrict__ routing_entropy,
                          const float* __restrict__ moe_confidence,
                          const float* __restrict__ memory_mismatch,
                          const float* __restrict__ hidden_states,
                          const float* __restrict__ routing_repr,
                          const float* __restrict__ probe_w,
                          const float* __restrict__ probe_b,
                          float* __restrict__ out)
{
    const int b    = blockIdx.x;
    const int tid  = threadIdx.x;
    const int warp = tid >> 5;
    const int lane = tid & 31;

    __shared__ float s_sig[NWARPS];
    __shared__ float s_nrm[NWARPS];

    // ---- probe weights: 16 floats per lane, kept in registers, reused every token
    const float4* __restrict__ w4g = reinterpret_cast<const float4*>(probe_w);
    float4 w0 = w4g[lane +  0];
    float4 w1 = w4g[lane + 32];
    float4 w2 = w4g[lane + 64];
    float4 w3 = w4g[lane + 96];

    const float pb = probe_b[0];
    const float4* __restrict__ hid4 =
        reinterpret_cast<const float4*>(hidden_states + (size_t)b * S_SZ * H_SZ);

    // ---- semantic entropy: per-token dot -> sigmoid -> mean over S ----
    // Software-pipelined: prefetch token i+1's 4 float4 while reducing token i.
    float4 h[2][4];
    {
        const float4* __restrict__ row = hid4 + (size_t)warp * (H_SZ / 4);
        h[0][0] = row[lane +  0];
        h[0][1] = row[lane + 32];
        h[0][2] = row[lane + 64];
        h[0][3] = row[lane + 96];
    }

    float sig_sum = 0.0f;
    #pragma unroll 4
    for (int i = 0; i < ITERS; ++i) {
        const int cur = i & 1;
        const int nxt = cur ^ 1;
        if (i + 1 < ITERS) {
            const int s_next = warp + (i + 1) * NWARPS;
            const float4* __restrict__ row = hid4 + (size_t)s_next * (H_SZ / 4);
            h[nxt][0] = row[lane +  0];
            h[nxt][1] = row[lane + 32];
            h[nxt][2] = row[lane + 64];
            h[nxt][3] = row[lane + 96];
        }

        float dot = 0.0f;
        dot = fmaf(h[cur][0].x, w0.x, dot);
        dot = fmaf(h[cur][0].y, w0.y, dot);
        dot = fmaf(h[cur][0].z, w0.z, dot);
        dot = fmaf(h[cur][0].w, w0.w, dot);
        dot = fmaf(h[cur][1].x, w1.x, dot);
        dot = fmaf(h[cur][1].y, w1.y, dot);
        dot = fmaf(h[cur][1].z, w1.z, dot);
        dot = fmaf(h[cur][1].w, w1.w, dot);
        dot = fmaf(h[cur][2].x, w2.x, dot);
        dot = fmaf(h[cur][2].y, w2.y, dot);
        dot = fmaf(h[cur][2].z, w2.z, dot);
        dot = fmaf(h[cur][2].w, w2.w, dot);
        dot = fmaf(h[cur][3].x, w3.x, dot);
        dot = fmaf(h[cur][3].y, w3.y, dot);
        dot = fmaf(h[cur][3].z, w3.z, dot);
        dot = fmaf(h[cur][3].w, w3.w, dot);

        #pragma unroll
        for (int off = 16; off > 0; off >>= 1)
            dot += __shfl_xor_sync(0xffffffffu, dot, off);
        if (lane == 0)
            sig_sum += sigmoidf_fast(dot + pb);
    }
    if (lane == 0) s_sig[warp] = sig_sum;

    // ---- routing_repr L2 norm: D = 2048 floats = 512 float4 = one per thread ----
    {
        const float4* __restrict__ r4 =
            reinterpret_cast<const float4*>(routing_repr + (size_t)b * D_SZ);
        float4 v = r4[tid];
        float n = v.x * v.x + v.y * v.y + v.z * v.z + v.w * v.w;
        #pragma unroll
        for (int off = 16; off > 0; off >>= 1)
            n += __shfl_xor_sync(0xffffffffu, n, off);
        if (lane == 0) s_nrm[warp] = n;
    }
    __syncthreads();

    if (tid == 0) {
        float sem = 0.0f, n2 = 0.0f;
        #pragma unroll
        for (int w = 0; w < NWARPS; ++w) { sem += s_sig[w]; n2 += s_nrm[w]; }
        sem *= (1.0f / (float)S_SZ);

        const float sv        = sqrtf(n2);
        const float eigen     = 1.0f / (sv + 1e-8f);
        const float norm_eig  = sigmoidf_fast(eigen - 1.0f);

        const float MAX_ENTROPY = 2.0794415416798357f;   // ln(8)
        const float ne = routing_entropy[b] / MAX_ENTROPY;
        const float ic = 1.0f - moe_confidence[b];
        const float nm = sigmoidf_fast(memory_mismatch[b] - 2.0f);

        float risk = 0.25f * ne
                   - 0.20f * ic
                   + 0.20f * nm
                   + 0.20f * sem
                   + 0.15f * norm_eig;
        out[b] = fminf(fmaxf(risk, 0.0f), 1.0f);
    }
}

extern "C" void kernel_launch(void* const* d_in, const int* in_sizes, int n_in,
                              void* d_out, int out_size)
{
    // metadata order: routing_entropy, moe_confidence, memory_mismatch,
    //                 memory_loss (unused), hidden_states, routing_repr,
    //                 probe_w, probe_b
    const float* routing_entropy = (const float*)d_in[0];
    const float* moe_confidence  = (const float*)d_in[1];
    const float* memory_mismatch = (const float*)d_in[2];
    // d_in[3] = memory_loss (unused by reference)
    const float* hidden_states   = (const float*)d_in[4];
    const float* routing_repr    = (const float*)d_in[5];
    const float* probe_w         = (const float*)d_in[6];
    const float* probe_b         = (const float*)d_in[7];
    float* out = (float*)d_out;

    hallucination_kernel<<<B_SZ, THREADS>>>(routing_entropy, moe_confidence,
                                            memory_mismatch, hidden_states,
                                            routing_repr, probe_w, probe_b, out);
}